// round 2
// baseline (speedup 1.0000x reference)
#include <cuda_runtime.h>
#include <cuda_bf16.h>
#include <cstdint>

// Problem constants
#define NN     16384
#define EE     262144
#define F_IN   1024
#define H1     256
#define NZ     64

// Scratch (allocation-free rule: __device__ globals)
__device__ float g_support1[NN * H1];   // x @ W1            (16 MB)
__device__ float g_h1[NN * H1];         // relu(spmm(...))   (16 MB)
__device__ float g_support2[NN * NZ];   // h1 @ W2           (4 MB)

// ---------------------------------------------------------------------------
// Generic tiled SGEMM: C[M,Ncols] = A[M,K] @ B[K,Ncols], all row-major fp32.
// BM=BN=64, BK=16, 256 threads, 4x4 per thread.
// ---------------------------------------------------------------------------
__global__ void sgemm64(const float* __restrict__ A, const float* __restrict__ B,
                        float* __restrict__ C, int M, int Ncols, int K) {
    __shared__ float As[64][16];
    __shared__ float Bs[16][64];

    const int tx = threadIdx.x & 15;
    const int ty = threadIdx.x >> 4;
    const int row0 = blockIdx.y * 64;
    const int col0 = blockIdx.x * 64;

    const int la_r = threadIdx.x >> 2;          // 0..63
    const int la_c = (threadIdx.x & 3) * 4;     // 0,4,8,12
    const int lb_r = threadIdx.x >> 4;          // 0..15
    const int lb_c = (threadIdx.x & 15) * 4;    // 0..60

    float acc[4][4] = {};

    for (int k0 = 0; k0 < K; k0 += 16) {
        float4 av = *(const float4*)&A[(size_t)(row0 + la_r) * K + k0 + la_c];
        *(float4*)&As[la_r][la_c] = av;
        float4 bv = *(const float4*)&B[(size_t)(k0 + lb_r) * Ncols + col0 + lb_c];
        *(float4*)&Bs[lb_r][lb_c] = bv;
        __syncthreads();

#pragma unroll
        for (int k = 0; k < 16; k++) {
            float a[4], b[4];
#pragma unroll
            for (int m = 0; m < 4; m++) a[m] = As[ty * 4 + m][k];
#pragma unroll
            for (int n = 0; n < 4; n++) b[n] = Bs[k][tx * 4 + n];
#pragma unroll
            for (int m = 0; m < 4; m++)
#pragma unroll
                for (int n = 0; n < 4; n++)
                    acc[m][n] = fmaf(a[m], b[n], acc[m][n]);
        }
        __syncthreads();
    }

#pragma unroll
    for (int m = 0; m < 4; m++) {
        float4 v = make_float4(acc[m][0], acc[m][1], acc[m][2], acc[m][3]);
        *(float4*)&C[(size_t)(row0 + ty * 4 + m) * Ncols + col0 + tx * 4] = v;
    }
}

// ---------------------------------------------------------------------------
// SpMM d=256: one block (256 threads) per edge.
// out[dst*256 + t] += w * in[src*256 + t]
// ---------------------------------------------------------------------------
__global__ void spmm_d256(const int* __restrict__ src, const int* __restrict__ dst,
                          const float* __restrict__ w, const float* __restrict__ in,
                          float* __restrict__ out) {
    const int e = blockIdx.x;
    const int s = src[e];
    const int d = dst[e];
    const float ww = w[e];
    const int t = threadIdx.x;
    atomicAdd(&out[(size_t)d * 256 + t], ww * in[(size_t)s * 256 + t]);
}

// ---------------------------------------------------------------------------
// SpMM d=64: 4 edges per 256-thread block.
// ---------------------------------------------------------------------------
__global__ void spmm_d64(const int* __restrict__ src, const int* __restrict__ dst,
                         const float* __restrict__ w, const float* __restrict__ in,
                         float* __restrict__ out) {
    const int e = blockIdx.x * 4 + (threadIdx.x >> 6);
    const int lane = threadIdx.x & 63;
    const int s = src[e];
    const int d = dst[e];
    const float ww = w[e];
    atomicAdd(&out[(size_t)d * 64 + lane], ww * in[(size_t)s * 64 + lane]);
}

// ---------------------------------------------------------------------------
// Utility kernels
// ---------------------------------------------------------------------------
__global__ void zero_kernel(float* __restrict__ p, size_t n4) {
    size_t i = (size_t)blockIdx.x * blockDim.x + threadIdx.x;
    float4 z = make_float4(0.f, 0.f, 0.f, 0.f);
    for (; i < n4; i += (size_t)gridDim.x * blockDim.x)
        ((float4*)p)[i] = z;
}

__global__ void relu_kernel(float* __restrict__ p, size_t n4) {
    size_t i = (size_t)blockIdx.x * blockDim.x + threadIdx.x;
    for (; i < n4; i += (size_t)gridDim.x * blockDim.x) {
        float4 v = ((float4*)p)[i];
        v.x = fmaxf(v.x, 0.f); v.y = fmaxf(v.y, 0.f);
        v.z = fmaxf(v.z, 0.f); v.w = fmaxf(v.w, 0.f);
        ((float4*)p)[i] = v;
    }
}

// ---------------------------------------------------------------------------
// Decoder: a_bar[i,j] = dot(z[i,:], z[j,:]), K=64 fully resident in smem.
// 64x64 output tile per block, 256 threads, 4x4 per thread.
// Both z tiles stored k-major (transposed on store) with +1 pad.
// ---------------------------------------------------------------------------
__global__ void decoder_kernel(const float* __restrict__ z, float* __restrict__ out) {
    __shared__ float Zi[64][65];   // Zi[k][i]
    __shared__ float Zj[64][65];   // Zj[k][j]

    const int i0 = blockIdx.y * 64;
    const int j0 = blockIdx.x * 64;
    const int tx = threadIdx.x & 15;
    const int ty = threadIdx.x >> 4;

    // 64 rows x 16 float4 = 1024 float4 loads per tile, 256 threads -> 4 each
    for (int t = threadIdx.x; t < 64 * 16; t += 256) {
        const int r  = t >> 4;
        const int c4 = (t & 15) * 4;
        float4 vi = *(const float4*)&z[(size_t)(i0 + r) * 64 + c4];
        Zi[c4 + 0][r] = vi.x; Zi[c4 + 1][r] = vi.y;
        Zi[c4 + 2][r] = vi.z; Zi[c4 + 3][r] = vi.w;
        float4 vj = *(const float4*)&z[(size_t)(j0 + r) * 64 + c4];
        Zj[c4 + 0][r] = vj.x; Zj[c4 + 1][r] = vj.y;
        Zj[c4 + 2][r] = vj.z; Zj[c4 + 3][r] = vj.w;
    }
    __syncthreads();

    float acc[4][4] = {};
#pragma unroll
    for (int k = 0; k < 64; k++) {
        float a[4], b[4];
#pragma unroll
        for (int m = 0; m < 4; m++) a[m] = Zi[k][ty * 4 + m];
#pragma unroll
        for (int n = 0; n < 4; n++) b[n] = Zj[k][tx * 4 + n];
#pragma unroll
        for (int m = 0; m < 4; m++)
#pragma unroll
            for (int n = 0; n < 4; n++)
                acc[m][n] = fmaf(a[m], b[n], acc[m][n]);
    }

#pragma unroll
    for (int m = 0; m < 4; m++) {
        float4 v = make_float4(acc[m][0], acc[m][1], acc[m][2], acc[m][3]);
        *(float4*)&out[(size_t)(i0 + ty * 4 + m) * NN + j0 + tx * 4] = v;
    }
}

// ---------------------------------------------------------------------------
// Launch: inputs per metadata order: x, W1, W2, edge_weight, edge_index
// Output: concat(a_bar [N*N], z [N*NZ])
// ---------------------------------------------------------------------------
extern "C" void kernel_launch(void* const* d_in, const int* in_sizes, int n_in,
                              void* d_out, int out_size) {
    const float* x  = (const float*)d_in[0];
    const float* W1 = (const float*)d_in[1];
    const float* W2 = (const float*)d_in[2];
    const float* ew = (const float*)d_in[3];
    const int* eidx = (const int*)d_in[4];
    const int* src = eidx;
    const int* dst = eidx + EE;

    float* a_bar = (float*)d_out;
    float* z = (float*)d_out + ((size_t)out_size - (size_t)NN * NZ);

    float* s1;  cudaGetSymbolAddress((void**)&s1, g_support1);
    float* h1;  cudaGetSymbolAddress((void**)&h1, g_h1);
    float* s2;  cudaGetSymbolAddress((void**)&s2, g_support2);

    // 1) support1 = x @ W1   [16384,1024] x [1024,256]
    {
        dim3 grid(H1 / 64, NN / 64);
        sgemm64<<<grid, 256>>>(x, W1, s1, NN, H1, F_IN);
    }

    // 2) h1 = 0; spmm; relu
    zero_kernel<<<1024, 256>>>(h1, (size_t)NN * H1 / 4);
    spmm_d256<<<EE, 256>>>(src, dst, ew, s1, h1);
    relu_kernel<<<1024, 256>>>(h1, (size_t)NN * H1 / 4);

    // 3) support2 = h1 @ W2  [16384,256] x [256,64]
    {
        dim3 grid(NZ / 64, NN / 64);
        sgemm64<<<grid, 256>>>(h1, W2, s2, NN, NZ, H1);
    }

    // 4) z = 0; spmm; relu  (z lives in tail of d_out)
    zero_kernel<<<256, 256>>>(z, (size_t)NN * NZ / 4);
    spmm_d64<<<EE / 4, 256>>>(src, dst, ew, s2, z);
    relu_kernel<<<256, 256>>>(z, (size_t)NN * NZ / 4);

    // 5) a_bar = z @ z.T
    {
        dim3 grid(NN / 64, NN / 64);
        decoder_kernel<<<grid, 256>>>(z, a_bar);
    }
}

// round 7
// speedup vs baseline: 1.5903x; 1.5903x over previous
#include <cuda_runtime.h>
#include <cuda_bf16.h>
#include <cstdint>

// Problem constants
#define NN     16384
#define EE     262144
#define F_IN   1024
#define H1     256
#define NZ     64

// ---------------------------------------------------------------------------
// Scratch (__device__ globals; allocation-free rule)
// ---------------------------------------------------------------------------
__device__ __nv_bfloat16 g_x_hi[NN * F_IN];
__device__ __nv_bfloat16 g_x_lo[NN * F_IN];
__device__ __nv_bfloat16 g_w1t_hi[H1 * F_IN];   // W1^T [256,1024]
__device__ __nv_bfloat16 g_w1t_lo[H1 * F_IN];
__device__ __nv_bfloat16 g_w2t_hi[NZ * H1];     // W2^T [64,256]
__device__ __nv_bfloat16 g_w2t_lo[NZ * H1];
__device__ float         g_s1[NN * H1];
__device__ float         g_h1[NN * H1];
__device__ __nv_bfloat16 g_h1_hi[NN * H1];
__device__ __nv_bfloat16 g_h1_lo[NN * H1];
__device__ float         g_s2[NN * NZ];
__device__ __nv_bfloat16 g_z_hi[NN * NZ];
__device__ __nv_bfloat16 g_z_lo[NN * NZ];

// ---------------------------------------------------------------------------
// mma.sync helpers (sm_80+ instructions, valid on base sm_103 target)
// ---------------------------------------------------------------------------
__device__ __forceinline__ void ldsm4(uint32_t& r0, uint32_t& r1, uint32_t& r2,
                                      uint32_t& r3, uint32_t saddr) {
    asm volatile("ldmatrix.sync.aligned.m8n8.x4.shared.b16 {%0,%1,%2,%3}, [%4];"
                 : "=r"(r0), "=r"(r1), "=r"(r2), "=r"(r3) : "r"(saddr));
}

__device__ __forceinline__ void mma16816(float* d, const uint32_t* a, const uint32_t* b) {
    asm volatile(
        "mma.sync.aligned.m16n8k16.row.col.f32.bf16.bf16.f32 "
        "{%0,%1,%2,%3}, {%4,%5,%6,%7}, {%8,%9}, {%0,%1,%2,%3};"
        : "+f"(d[0]), "+f"(d[1]), "+f"(d[2]), "+f"(d[3])
        : "r"(a[0]), "r"(a[1]), "r"(a[2]), "r"(a[3]), "r"(b[0]), "r"(b[1]));
}

// ---------------------------------------------------------------------------
// mma_gemm<BN>: C[128, BN] per block = sum_k A[m,k]*B[n,k]
//   A (split Ah/Al) rows [M,K] K-major; B (split Bh/Bl) rows [NB,K] K-major.
//   Split-bf16: D = Ah*Bh + Ah*Bl + Al*Bh (fp32 accum).
//   256 threads = 8 warps (4 in M x 2 in N). Warp tile 32 x BN/2. BK = 32.
//   Smem rows padded to 40 bf16 (80 B) -> ldmatrix conflict-free permutation.
// ---------------------------------------------------------------------------
template <int BN>
__global__ __launch_bounds__(256)
void mma_gemm(const __nv_bfloat16* __restrict__ Ah,
              const __nv_bfloat16* __restrict__ Al,
              const __nv_bfloat16* __restrict__ Bh,
              const __nv_bfloat16* __restrict__ Bl,
              float* __restrict__ C, int K, int ldC) {
    constexpr int PAD = 40;            // 32 + 8 bf16
    constexpr int NT  = BN / 16;       // n8-tiles per warp
    __shared__ __align__(16) __nv_bfloat16 sA[2][128][PAD];  // [hi/lo][row][k]
    __shared__ __align__(16) __nv_bfloat16 sB[2][BN][PAD];

    const int tid  = threadIdx.x;
    const int lane = tid & 31;
    const int warp = tid >> 5;
    const int wm   = warp & 3;          // 0..3 -> M offset wm*32
    const int wn   = warp >> 2;         // 0..1 -> N offset wn*(BN/2)
    const int i0 = blockIdx.y * 128;
    const int j0 = blockIdx.x * BN;

    float acc[2][NT][4];
#pragma unroll
    for (int mi = 0; mi < 2; mi++)
#pragma unroll
        for (int ni = 0; ni < NT; ni++)
#pragma unroll
            for (int q = 0; q < 4; q++) acc[mi][ni][q] = 0.f;

    // Precompute ldmatrix lane-address components
    const int a_row = ((lane >> 3) & 1) * 8 + (lane & 7);  // row within m16 tile
    const int a_col = (lane >> 4) * 8;                     // k offset 0/8
    const int b_row = (lane >> 4) * 8 + (lane & 7);        // n within 16-row pair
    const int b_col = ((lane >> 3) & 1) * 8;               // k offset 0/8

    const int nchunks = K >> 5;
    for (int ch = 0; ch < nchunks; ch++) {
        const int k0 = ch << 5;
        // ---- global -> smem (16B per op) ----
#pragma unroll 1
        for (int t = tid; t < 128 * 4; t += 256) {
            const int r = t >> 2, c = (t & 3) * 8;
            const size_t gi = (size_t)(i0 + r) * K + k0 + c;
            *(uint4*)&sA[0][r][c] = *(const uint4*)&Ah[gi];
            *(uint4*)&sA[1][r][c] = *(const uint4*)&Al[gi];
        }
#pragma unroll 1
        for (int t = tid; t < BN * 4; t += 256) {
            const int r = t >> 2, c = (t & 3) * 8;
            const size_t gi = (size_t)(j0 + r) * K + k0 + c;
            *(uint4*)&sB[0][r][c] = *(const uint4*)&Bh[gi];
            *(uint4*)&sB[1][r][c] = *(const uint4*)&Bl[gi];
        }
        __syncthreads();

#pragma unroll
        for (int ks = 0; ks < 2; ks++) {
            const int kk = ks * 16;
            // A fragments: 2 m16-tiles x {hi,lo}
            uint32_t ah[2][4], al[2][4];
#pragma unroll
            for (int mi = 0; mi < 2; mi++) {
                const int row = wm * 32 + mi * 16 + a_row;
                uint32_t ad0 = (uint32_t)__cvta_generic_to_shared(
                    &sA[0][row][kk + a_col]);
                ldsm4(ah[mi][0], ah[mi][1], ah[mi][2], ah[mi][3], ad0);
                uint32_t ad1 = (uint32_t)__cvta_generic_to_shared(
                    &sA[1][row][kk + a_col]);
                ldsm4(al[mi][0], al[mi][1], al[mi][2], al[mi][3], ad1);
            }
            // B fragments: NT n8-tiles x {hi,lo} (x4 covers two n8-tiles)
            uint32_t bh[NT][2], bl[NT][2];
#pragma unroll
            for (int p = 0; p < NT / 2; p++) {
                const int nrow = wn * (BN / 2) + p * 16 + b_row;
                uint32_t bd0 = (uint32_t)__cvta_generic_to_shared(
                    &sB[0][nrow][kk + b_col]);
                ldsm4(bh[2 * p][0], bh[2 * p][1], bh[2 * p + 1][0], bh[2 * p + 1][1], bd0);
                uint32_t bd1 = (uint32_t)__cvta_generic_to_shared(
                    &sB[1][nrow][kk + b_col]);
                ldsm4(bl[2 * p][0], bl[2 * p][1], bl[2 * p + 1][0], bl[2 * p + 1][1], bd1);
            }
            // MMAs: hh + hl + lh
#pragma unroll
            for (int mi = 0; mi < 2; mi++)
#pragma unroll
                for (int ni = 0; ni < NT; ni++) {
                    mma16816(acc[mi][ni], ah[mi], bh[ni]);
                    mma16816(acc[mi][ni], ah[mi], bl[ni]);
                    mma16816(acc[mi][ni], al[mi], bh[ni]);
                }
        }
        __syncthreads();
    }

    // ---- epilogue: fragment -> C (float2 stores) ----
    const int er = lane >> 2;           // 0..7
    const int ec = (lane & 3) * 2;      // 0,2,4,6
#pragma unroll
    for (int mi = 0; mi < 2; mi++) {
        const int r0 = i0 + wm * 32 + mi * 16 + er;
#pragma unroll
        for (int ni = 0; ni < NT; ni++) {
            const int c0 = j0 + wn * (BN / 2) + ni * 8 + ec;
            *(float2*)&C[(size_t)r0 * ldC + c0] =
                make_float2(acc[mi][ni][0], acc[mi][ni][1]);
            *(float2*)&C[(size_t)(r0 + 8) * ldC + c0] =
                make_float2(acc[mi][ni][2], acc[mi][ni][3]);
        }
    }
}

// ---------------------------------------------------------------------------
// Conversion kernels (fp32 -> bf16 hi/lo split, optional relu)
// ---------------------------------------------------------------------------
__global__ void split_kernel(const float* __restrict__ in,
                             __nv_bfloat16* __restrict__ hi,
                             __nv_bfloat16* __restrict__ lo,
                             size_t n, int relu) {
    for (size_t i = (size_t)blockIdx.x * blockDim.x + threadIdx.x; i < n;
         i += (size_t)gridDim.x * blockDim.x) {
        float v = in[i];
        if (relu) v = fmaxf(v, 0.f);
        __nv_bfloat16 h = __float2bfloat16_rn(v);
        hi[i] = h;
        lo[i] = __float2bfloat16_rn(v - __bfloat162float(h));
    }
}

__global__ void relu_split_kernel(float* __restrict__ z,
                                  __nv_bfloat16* __restrict__ hi,
                                  __nv_bfloat16* __restrict__ lo, size_t n) {
    for (size_t i = (size_t)blockIdx.x * blockDim.x + threadIdx.x; i < n;
         i += (size_t)gridDim.x * blockDim.x) {
        float v = fmaxf(z[i], 0.f);
        z[i] = v;
        __nv_bfloat16 h = __float2bfloat16_rn(v);
        hi[i] = h;
        lo[i] = __float2bfloat16_rn(v - __bfloat162float(h));
    }
}

// transpose-split: in [R,C] -> out [C,R]
__global__ void tsplit_kernel(const float* __restrict__ in,
                              __nv_bfloat16* __restrict__ hi,
                              __nv_bfloat16* __restrict__ lo, int R, int C) {
    for (int i = blockIdx.x * blockDim.x + threadIdx.x; i < R * C;
         i += gridDim.x * blockDim.x) {
        int r = i / C, c = i % C;
        float v = in[i];
        __nv_bfloat16 h = __float2bfloat16_rn(v);
        hi[(size_t)c * R + r] = h;
        lo[(size_t)c * R + r] = __float2bfloat16_rn(v - __bfloat162float(h));
    }
}

// ---------------------------------------------------------------------------
// SpMM (edge-parallel atomics) + utils
// ---------------------------------------------------------------------------
__global__ void spmm_d256(const int* __restrict__ src, const int* __restrict__ dst,
                          const float* __restrict__ w, const float* __restrict__ in,
                          float* __restrict__ out) {
    const int e = blockIdx.x;
    const int s = src[e], d = dst[e];
    const float ww = w[e];
    const int t = threadIdx.x;
    atomicAdd(&out[(size_t)d * 256 + t], ww * in[(size_t)s * 256 + t]);
}

__global__ void spmm_d64(const int* __restrict__ src, const int* __restrict__ dst,
                         const float* __restrict__ w, const float* __restrict__ in,
                         float* __restrict__ out) {
    const int e = blockIdx.x * 4 + (threadIdx.x >> 6);
    const int lane = threadIdx.x & 63;
    const int s = src[e], d = dst[e];
    const float ww = w[e];
    atomicAdd(&out[(size_t)d * 64 + lane], ww * in[(size_t)s * 64 + lane]);
}

__global__ void zero_kernel(float* __restrict__ p, size_t n4) {
    size_t i = (size_t)blockIdx.x * blockDim.x + threadIdx.x;
    float4 zv = make_float4(0.f, 0.f, 0.f, 0.f);
    for (; i < n4; i += (size_t)gridDim.x * blockDim.x) ((float4*)p)[i] = zv;
}

// ---------------------------------------------------------------------------
// Launch. Inputs: x, W1, W2, edge_weight, edge_index. Out: [a_bar | z].
// ---------------------------------------------------------------------------
extern "C" void kernel_launch(void* const* d_in, const int* in_sizes, int n_in,
                              void* d_out, int out_size) {
    const float* x  = (const float*)d_in[0];
    const float* W1 = (const float*)d_in[1];
    const float* W2 = (const float*)d_in[2];
    const float* ew = (const float*)d_in[3];
    const int* eidx = (const int*)d_in[4];
    const int* src = eidx;
    const int* dst = eidx + EE;

    float* a_bar = (float*)d_out;
    float* z = (float*)d_out + ((size_t)out_size - (size_t)NN * NZ);

    __nv_bfloat16 *x_hi, *x_lo, *w1t_hi, *w1t_lo, *w2t_hi, *w2t_lo;
    __nv_bfloat16 *h1_hi, *h1_lo, *z_hi, *z_lo;
    float *s1, *h1, *s2;
    cudaGetSymbolAddress((void**)&x_hi, g_x_hi);
    cudaGetSymbolAddress((void**)&x_lo, g_x_lo);
    cudaGetSymbolAddress((void**)&w1t_hi, g_w1t_hi);
    cudaGetSymbolAddress((void**)&w1t_lo, g_w1t_lo);
    cudaGetSymbolAddress((void**)&w2t_hi, g_w2t_hi);
    cudaGetSymbolAddress((void**)&w2t_lo, g_w2t_lo);
    cudaGetSymbolAddress((void**)&s1, g_s1);
    cudaGetSymbolAddress((void**)&h1, g_h1);
    cudaGetSymbolAddress((void**)&h1_hi, g_h1_hi);
    cudaGetSymbolAddress((void**)&h1_lo, g_h1_lo);
    cudaGetSymbolAddress((void**)&s2, g_s2);
    cudaGetSymbolAddress((void**)&z_hi, g_z_hi);
    cudaGetSymbolAddress((void**)&z_lo, g_z_lo);

    // 0) conversions for layer 1
    split_kernel<<<2048, 256>>>(x, x_hi, x_lo, (size_t)NN * F_IN, 0);
    tsplit_kernel<<<512, 256>>>(W1, w1t_hi, w1t_lo, F_IN, H1);

    // 1) s1 = x @ W1   (M=16384, N=256, K=1024)
    {
        dim3 grid(H1 / 128, NN / 128);
        mma_gemm<128><<<grid, 256>>>(x_hi, x_lo, w1t_hi, w1t_lo, s1, F_IN, H1);
    }

    // 2) h1 = spmm(s1); split with relu
    zero_kernel<<<1024, 256>>>(h1, (size_t)NN * H1 / 4);
    spmm_d256<<<EE, 256>>>(src, dst, ew, s1, h1);
    split_kernel<<<1024, 256>>>(h1, h1_hi, h1_lo, (size_t)NN * H1, 1);

    // 3) s2 = relu(h1) @ W2  (M=16384, N=64, K=256)
    tsplit_kernel<<<64, 256>>>(W2, w2t_hi, w2t_lo, H1, NZ);
    {
        dim3 grid(1, NN / 128);
        mma_gemm<64><<<grid, 256>>>(h1_hi, h1_lo, w2t_hi, w2t_lo, s2, H1, NZ);
    }

    // 4) z = relu(spmm(s2))  (z in tail of d_out), split
    zero_kernel<<<256, 256>>>(z, (size_t)NN * NZ / 4);
    spmm_d64<<<EE / 4, 256>>>(src, dst, ew, s2, z);
    relu_split_kernel<<<512, 256>>>(z, z_hi, z_lo, (size_t)NN * NZ);

    // 5) a_bar = z @ z.T  (M=16384, N=16384, K=64)
    {
        dim3 grid(NN / 128, NN / 128);
        mma_gemm<128><<<grid, 256>>>(z_hi, z_lo, z_hi, z_lo, a_bar, NZ, NN);
    }
}

// round 8
// speedup vs baseline: 2.7025x; 1.6994x over previous
#include <cuda_runtime.h>
#include <cuda_bf16.h>
#include <cstdint>

// Problem constants
#define NN     16384
#define EE     262144
#define F_IN   1024
#define H1     256
#define NZ     64

// ---------------------------------------------------------------------------
// Scratch (__device__ globals; allocation-free rule)
// ---------------------------------------------------------------------------
__device__ __nv_bfloat16 g_x_hi[NN * F_IN];
__device__ __nv_bfloat16 g_x_lo[NN * F_IN];
__device__ __nv_bfloat16 g_w1t_hi[H1 * F_IN];   // W1^T [256,1024]
__device__ __nv_bfloat16 g_w1t_lo[H1 * F_IN];
__device__ __nv_bfloat16 g_w2t_hi[NZ * H1];     // W2^T [64,256]
__device__ __nv_bfloat16 g_w2t_lo[NZ * H1];
__device__ float         g_s1[NN * H1];
__device__ __nv_bfloat16 g_h1_hi[NN * H1];
__device__ __nv_bfloat16 g_h1_lo[NN * H1];
__device__ float         g_s2[NN * NZ];
__device__ __nv_bfloat16 g_z_hi[NN * NZ];
__device__ __nv_bfloat16 g_z_lo[NN * NZ];
// CSR build
__device__ int g_cnt[NN];
__device__ int g_rowptr[NN + 1];
__device__ int g_fill[NN];
__device__ int g_perm[EE];

// ---------------------------------------------------------------------------
// mma.sync / cp.async helpers (sm_80+ instructions, valid on base sm_103)
// ---------------------------------------------------------------------------
__device__ __forceinline__ void ldsm4(uint32_t& r0, uint32_t& r1, uint32_t& r2,
                                      uint32_t& r3, uint32_t saddr) {
    asm volatile("ldmatrix.sync.aligned.m8n8.x4.shared.b16 {%0,%1,%2,%3}, [%4];"
                 : "=r"(r0), "=r"(r1), "=r"(r2), "=r"(r3) : "r"(saddr));
}

__device__ __forceinline__ void mma16816(float* d, const uint32_t* a, const uint32_t* b) {
    asm volatile(
        "mma.sync.aligned.m16n8k16.row.col.f32.bf16.bf16.f32 "
        "{%0,%1,%2,%3}, {%4,%5,%6,%7}, {%8,%9}, {%0,%1,%2,%3};"
        : "+f"(d[0]), "+f"(d[1]), "+f"(d[2]), "+f"(d[3])
        : "r"(a[0]), "r"(a[1]), "r"(a[2]), "r"(a[3]), "r"(b[0]), "r"(b[1]));
}

__device__ __forceinline__ void cp16(void* sdst, const void* gsrc) {
    uint32_t sa = (uint32_t)__cvta_generic_to_shared(sdst);
    asm volatile("cp.async.cg.shared.global [%0], [%1], 16;" :: "r"(sa), "l"(gsrc));
}
#define CP_COMMIT() asm volatile("cp.async.commit_group;" ::: "memory")
#define CP_WAIT0()  asm volatile("cp.async.wait_group 0;" ::: "memory")
#define CP_WAIT1()  asm volatile("cp.async.wait_group 1;" ::: "memory")

// ---------------------------------------------------------------------------
// mma_gemm_db<BN>: C[128, BN] per block = sum_k A[m,k]*B[n,k] (both K-major,
// split bf16: D = Ah*Bh + Ah*Bl + Al*Bh). 256 threads = 8 warps (4M x 2N),
// warp tile 32 x BN/2, BK=32, cp.async double-buffered.
// Smem rows padded to 40 bf16 (80 B, multiple of 16) -> conflict-free ldmatrix.
// ---------------------------------------------------------------------------
template <int BN>
__global__ __launch_bounds__(256)
void mma_gemm_db(const __nv_bfloat16* __restrict__ Ah,
                 const __nv_bfloat16* __restrict__ Al,
                 const __nv_bfloat16* __restrict__ Bh,
                 const __nv_bfloat16* __restrict__ Bl,
                 float* __restrict__ C, int K, int ldC) {
    constexpr int PAD  = 40;
    constexpr int NT   = BN / 16;              // n8-tile pairs per warp? (n8 tiles = NT)
    constexpr int A_ST = 2 * 128 * PAD;        // bf16 elems (hi+lo) per stage
    constexpr int B_ST = 2 * BN * PAD;
    constexpr int STG  = A_ST + B_ST;

    extern __shared__ __align__(16) char dyn[];
    __nv_bfloat16* sm = (__nv_bfloat16*)dyn;

    const int tid  = threadIdx.x;
    const int lane = tid & 31;
    const int warp = tid >> 5;
    const int wm   = warp & 3;
    const int wn   = warp >> 2;
    const int i0 = blockIdx.y * 128;
    const int j0 = blockIdx.x * BN;

    float acc[2][NT][4];
#pragma unroll
    for (int mi = 0; mi < 2; mi++)
#pragma unroll
        for (int ni = 0; ni < NT; ni++)
#pragma unroll
            for (int q = 0; q < 4; q++) acc[mi][ni][q] = 0.f;

    const int a_row = ((lane >> 3) & 1) * 8 + (lane & 7);
    const int a_col = (lane >> 4) * 8;
    const int b_row = (lane >> 4) * 8 + (lane & 7);
    const int b_col = ((lane >> 3) & 1) * 8;

    auto load_stage = [&](int st, int k0) {
        __nv_bfloat16* base = sm + st * STG;
#pragma unroll
        for (int t = tid; t < 128 * 4; t += 256) {
            const int r = t >> 2, c = (t & 3) * 8;
            const size_t gi = (size_t)(i0 + r) * K + k0 + c;
            cp16(base + r * PAD + c, Ah + gi);
            cp16(base + 128 * PAD + r * PAD + c, Al + gi);
        }
#pragma unroll
        for (int t = tid; t < BN * 4; t += 256) {
            const int r = t >> 2, c = (t & 3) * 8;
            const size_t gi = (size_t)(j0 + r) * K + k0 + c;
            cp16(base + A_ST + r * PAD + c, Bh + gi);
            cp16(base + A_ST + BN * PAD + r * PAD + c, Bl + gi);
        }
    };

    const int nchunks = K >> 5;
    load_stage(0, 0);
    CP_COMMIT();

    for (int ch = 0; ch < nchunks; ch++) {
        if (ch + 1 < nchunks) {
            load_stage((ch + 1) & 1, (ch + 1) << 5);
            CP_COMMIT();
            CP_WAIT1();
        } else {
            CP_WAIT0();
        }
        __syncthreads();

        __nv_bfloat16* base = sm + (ch & 1) * STG;
        __nv_bfloat16* bA[2] = {base, base + 128 * PAD};
        __nv_bfloat16* bB[2] = {base + A_ST, base + A_ST + BN * PAD};

#pragma unroll
        for (int ks = 0; ks < 2; ks++) {
            const int kk = ks * 16;
            uint32_t ah[2][4], al[2][4];
#pragma unroll
            for (int mi = 0; mi < 2; mi++) {
                const int row = wm * 32 + mi * 16 + a_row;
                ldsm4(ah[mi][0], ah[mi][1], ah[mi][2], ah[mi][3],
                      (uint32_t)__cvta_generic_to_shared(bA[0] + row * PAD + kk + a_col));
                ldsm4(al[mi][0], al[mi][1], al[mi][2], al[mi][3],
                      (uint32_t)__cvta_generic_to_shared(bA[1] + row * PAD + kk + a_col));
            }
            uint32_t bh[NT][2], bl[NT][2];
#pragma unroll
            for (int p = 0; p < NT / 2; p++) {
                const int nrow = wn * (BN / 2) + p * 16 + b_row;
                ldsm4(bh[2 * p][0], bh[2 * p][1], bh[2 * p + 1][0], bh[2 * p + 1][1],
                      (uint32_t)__cvta_generic_to_shared(bB[0] + nrow * PAD + kk + b_col));
                ldsm4(bl[2 * p][0], bl[2 * p][1], bl[2 * p + 1][0], bl[2 * p + 1][1],
                      (uint32_t)__cvta_generic_to_shared(bB[1] + nrow * PAD + kk + b_col));
            }
#pragma unroll
            for (int mi = 0; mi < 2; mi++)
#pragma unroll
                for (int ni = 0; ni < NT; ni++) {
                    mma16816(acc[mi][ni], ah[mi], bh[ni]);
                    mma16816(acc[mi][ni], ah[mi], bl[ni]);
                    mma16816(acc[mi][ni], al[mi], bh[ni]);
                }
        }
        __syncthreads();
    }

    const int er = lane >> 2;
    const int ec = (lane & 3) * 2;
#pragma unroll
    for (int mi = 0; mi < 2; mi++) {
        const int r0 = i0 + wm * 32 + mi * 16 + er;
#pragma unroll
        for (int ni = 0; ni < NT; ni++) {
            const int c0 = j0 + wn * (BN / 2) + ni * 8 + ec;
            *(float2*)&C[(size_t)r0 * ldC + c0] = make_float2(acc[mi][ni][0], acc[mi][ni][1]);
            *(float2*)&C[(size_t)(r0 + 8) * ldC + c0] = make_float2(acc[mi][ni][2], acc[mi][ni][3]);
        }
    }
}

// ---------------------------------------------------------------------------
// decoder_sym: a_bar = z @ z.T exploiting symmetry. Grid (128,128); blocks
// with bx < by exit. Block (by,bx) computes tile (i0=by*128, j0=bx*128),
// stages it in smem, stores it and (if off-diagonal) its transpose.
// K = 64 entirely resident. PAD=72 (row 144 B) -> conflict-free ldmatrix.
// ---------------------------------------------------------------------------
__global__ __launch_bounds__(256)
void decoder_sym(const __nv_bfloat16* __restrict__ Zh,
                 const __nv_bfloat16* __restrict__ Zl,
                 float* __restrict__ C) {
    constexpr int PAD = 72;
    extern __shared__ __align__(16) char dyn[];
    __nv_bfloat16* sm = (__nv_bfloat16*)dyn;   // Ah,Al,Bh,Bl: 4 x 128 x PAD
    float* stage = (float*)dyn;                // aliased after compute: 128 x 129

    const int bx = blockIdx.x, by = blockIdx.y;
    if (bx < by) return;
    const int i0 = by * 128;
    const int j0 = bx * 128;

    const int tid  = threadIdx.x;
    const int lane = tid & 31;
    const int warp = tid >> 5;
    const int wm   = warp & 3;
    const int wn   = warp >> 2;

    __nv_bfloat16* tA[2] = {sm, sm + 128 * PAD};
    __nv_bfloat16* tB[2] = {sm + 2 * 128 * PAD, sm + 3 * 128 * PAD};

    // load tiles (K=64 -> 8 x uint4 per row)
    for (int t = tid; t < 128 * 8; t += 256) {
        const int r = t >> 3, c = (t & 7) * 8;
        const size_t ga = (size_t)(i0 + r) * NZ + c;
        const size_t gb = (size_t)(j0 + r) * NZ + c;
        *(uint4*)(tA[0] + r * PAD + c) = *(const uint4*)&Zh[ga];
        *(uint4*)(tA[1] + r * PAD + c) = *(const uint4*)&Zl[ga];
        *(uint4*)(tB[0] + r * PAD + c) = *(const uint4*)&Zh[gb];
        *(uint4*)(tB[1] + r * PAD + c) = *(const uint4*)&Zl[gb];
    }
    __syncthreads();

    float acc[2][8][4];
#pragma unroll
    for (int mi = 0; mi < 2; mi++)
#pragma unroll
        for (int ni = 0; ni < 8; ni++)
#pragma unroll
            for (int q = 0; q < 4; q++) acc[mi][ni][q] = 0.f;

    const int a_row = ((lane >> 3) & 1) * 8 + (lane & 7);
    const int a_col = (lane >> 4) * 8;
    const int b_row = (lane >> 4) * 8 + (lane & 7);
    const int b_col = ((lane >> 3) & 1) * 8;

#pragma unroll
    for (int ks = 0; ks < 4; ks++) {
        const int kk = ks * 16;
        uint32_t ah[2][4], al[2][4];
#pragma unroll
        for (int mi = 0; mi < 2; mi++) {
            const int row = wm * 32 + mi * 16 + a_row;
            ldsm4(ah[mi][0], ah[mi][1], ah[mi][2], ah[mi][3],
                  (uint32_t)__cvta_generic_to_shared(tA[0] + row * PAD + kk + a_col));
            ldsm4(al[mi][0], al[mi][1], al[mi][2], al[mi][3],
                  (uint32_t)__cvta_generic_to_shared(tA[1] + row * PAD + kk + a_col));
        }
        uint32_t bh[8][2], bl[8][2];
#pragma unroll
        for (int p = 0; p < 4; p++) {
            const int nrow = wn * 64 + p * 16 + b_row;
            ldsm4(bh[2 * p][0], bh[2 * p][1], bh[2 * p + 1][0], bh[2 * p + 1][1],
                  (uint32_t)__cvta_generic_to_shared(tB[0] + nrow * PAD + kk + b_col));
            ldsm4(bl[2 * p][0], bl[2 * p][1], bl[2 * p + 1][0], bl[2 * p + 1][1],
                  (uint32_t)__cvta_generic_to_shared(tB[1] + nrow * PAD + kk + b_col));
        }
#pragma unroll
        for (int mi = 0; mi < 2; mi++)
#pragma unroll
            for (int ni = 0; ni < 8; ni++) {
                mma16816(acc[mi][ni], ah[mi], bh[ni]);
                mma16816(acc[mi][ni], ah[mi], bl[ni]);
                mma16816(acc[mi][ni], al[mi], bh[ni]);
            }
    }
    __syncthreads();   // all ldmatrix reads done before stage aliases tiles

    // stage fragments
    const int er = lane >> 2;
    const int ec = (lane & 3) * 2;
#pragma unroll
    for (int mi = 0; mi < 2; mi++) {
        const int r0 = wm * 32 + mi * 16 + er;
#pragma unroll
        for (int ni = 0; ni < 8; ni++) {
            const int c0 = wn * 64 + ni * 8 + ec;
            stage[r0 * 129 + c0]       = acc[mi][ni][0];
            stage[r0 * 129 + c0 + 1]   = acc[mi][ni][1];
            stage[(r0 + 8) * 129 + c0]     = acc[mi][ni][2];
            stage[(r0 + 8) * 129 + c0 + 1] = acc[mi][ni][3];
        }
    }
    __syncthreads();

    // coalesced stores: normal tile
    for (int t = tid; t < 128 * 32; t += 256) {
        const int r = t >> 5, c4 = (t & 31) * 4;
        float4 v = make_float4(stage[r * 129 + c4], stage[r * 129 + c4 + 1],
                               stage[r * 129 + c4 + 2], stage[r * 129 + c4 + 3]);
        *(float4*)&C[(size_t)(i0 + r) * NN + j0 + c4] = v;
    }
    // mirror tile (transposed read from smem)
    if (bx > by) {
        for (int t = tid; t < 128 * 32; t += 256) {
            const int r = t >> 5, c4 = (t & 31) * 4;
            float4 v = make_float4(stage[(c4 + 0) * 129 + r], stage[(c4 + 1) * 129 + r],
                                   stage[(c4 + 2) * 129 + r], stage[(c4 + 3) * 129 + r]);
            *(float4*)&C[(size_t)(j0 + r) * NN + i0 + c4] = v;
        }
    }
}

// ---------------------------------------------------------------------------
// Conversion kernels
// ---------------------------------------------------------------------------
__global__ void split_kernel(const float* __restrict__ in,
                             __nv_bfloat16* __restrict__ hi,
                             __nv_bfloat16* __restrict__ lo, size_t n) {
    for (size_t i = (size_t)blockIdx.x * blockDim.x + threadIdx.x; i < n;
         i += (size_t)gridDim.x * blockDim.x) {
        float v = in[i];
        __nv_bfloat16 h = __float2bfloat16_rn(v);
        hi[i] = h;
        lo[i] = __float2bfloat16_rn(v - __bfloat162float(h));
    }
}

__global__ void tsplit_kernel(const float* __restrict__ in,
                              __nv_bfloat16* __restrict__ hi,
                              __nv_bfloat16* __restrict__ lo, int R, int C) {
    for (int i = blockIdx.x * blockDim.x + threadIdx.x; i < R * C;
         i += gridDim.x * blockDim.x) {
        int r = i / C, c = i % C;
        float v = in[i];
        __nv_bfloat16 h = __float2bfloat16_rn(v);
        hi[(size_t)c * R + r] = h;
        lo[(size_t)c * R + r] = __float2bfloat16_rn(v - __bfloat162float(h));
    }
}

// ---------------------------------------------------------------------------
// CSR build
// ---------------------------------------------------------------------------
__global__ void zero_int(int* __restrict__ p, int n) {
    for (int i = blockIdx.x * blockDim.x + threadIdx.x; i < n;
         i += gridDim.x * blockDim.x) p[i] = 0;
}

__global__ void hist_kernel(const int* __restrict__ dst, int* __restrict__ cnt) {
    int e = blockIdx.x * blockDim.x + threadIdx.x;
    if (e < EE) atomicAdd(&cnt[dst[e]], 1);
}

__global__ void scan_kernel(const int* __restrict__ cnt, int* __restrict__ rowptr,
                            int* __restrict__ fill) {
    __shared__ int ssum[256];
    const int tid = threadIdx.x;
    const int base = tid * 64;
    int s = 0;
    for (int i = 0; i < 64; i++) s += cnt[base + i];
    ssum[tid] = s;
    __syncthreads();
    if (tid == 0) {
        int run = 0;
        for (int i = 0; i < 256; i++) { int t = ssum[i]; ssum[i] = run; run += t; }
        rowptr[NN] = run;
    }
    __syncthreads();
    int run = ssum[tid];
    for (int i = 0; i < 64; i++) {
        rowptr[base + i] = run;
        fill[base + i] = run;
        run += cnt[base + i];
    }
}

__global__ void scatter_kernel(const int* __restrict__ dst, int* __restrict__ fill,
                               int* __restrict__ perm) {
    int e = blockIdx.x * blockDim.x + threadIdx.x;
    if (e < EE) {
        int slot = atomicAdd(&fill[dst[e]], 1);
        perm[slot] = e;
    }
}

// ---------------------------------------------------------------------------
// CSR SpMM (no float atomics), fused relu + bf16 split epilogues
// ---------------------------------------------------------------------------
__global__ __launch_bounds__(256)
void spmm_csr_d256(const int* __restrict__ rowptr, const int* __restrict__ perm,
                   const int* __restrict__ src, const float* __restrict__ w,
                   const float* __restrict__ in,
                   __nv_bfloat16* __restrict__ hi, __nv_bfloat16* __restrict__ lo) {
    __shared__ int   s_s[256];
    __shared__ float s_w[256];
    const int row = blockIdx.x;
    const int t = threadIdx.x;
    const int start = rowptr[row], end = rowptr[row + 1];
    float acc = 0.f;
    for (int base = start; base < end; base += 256) {
        const int m = min(256, end - base);
        if (t < m) {
            const int e = perm[base + t];
            s_s[t] = src[e];
            s_w[t] = w[e];
        }
        __syncthreads();
        for (int i = 0; i < m; i++)
            acc += s_w[i] * in[(size_t)s_s[i] * 256 + t];
        __syncthreads();
    }
    float v = fmaxf(acc, 0.f);
    __nv_bfloat16 h = __float2bfloat16_rn(v);
    hi[(size_t)row * 256 + t] = h;
    lo[(size_t)row * 256 + t] = __float2bfloat16_rn(v - __bfloat162float(h));
}

__global__ __launch_bounds__(64)
void spmm_csr_d64(const int* __restrict__ rowptr, const int* __restrict__ perm,
                  const int* __restrict__ src, const float* __restrict__ w,
                  const float* __restrict__ in, float* __restrict__ z,
                  __nv_bfloat16* __restrict__ hi, __nv_bfloat16* __restrict__ lo) {
    const int row = blockIdx.x;
    const int t = threadIdx.x;
    const int start = rowptr[row], end = rowptr[row + 1];
    float acc = 0.f;
    for (int p = start; p < end; p++) {
        const int e = perm[p];
        acc += w[e] * in[(size_t)src[e] * 64 + t];
    }
    float v = fmaxf(acc, 0.f);
    z[(size_t)row * 64 + t] = v;
    __nv_bfloat16 h = __float2bfloat16_rn(v);
    hi[(size_t)row * 64 + t] = h;
    lo[(size_t)row * 64 + t] = __float2bfloat16_rn(v - __bfloat162float(h));
}

// ---------------------------------------------------------------------------
// Launch. Inputs: x, W1, W2, edge_weight, edge_index. Out: [a_bar | z].
// ---------------------------------------------------------------------------
extern "C" void kernel_launch(void* const* d_in, const int* in_sizes, int n_in,
                              void* d_out, int out_size) {
    const float* x  = (const float*)d_in[0];
    const float* W1 = (const float*)d_in[1];
    const float* W2 = (const float*)d_in[2];
    const float* ew = (const float*)d_in[3];
    const int* eidx = (const int*)d_in[4];
    const int* src = eidx;
    const int* dst = eidx + EE;

    float* a_bar = (float*)d_out;
    float* z = (float*)d_out + ((size_t)out_size - (size_t)NN * NZ);

    __nv_bfloat16 *x_hi, *x_lo, *w1t_hi, *w1t_lo, *w2t_hi, *w2t_lo;
    __nv_bfloat16 *h1_hi, *h1_lo, *z_hi, *z_lo;
    float *s1, *s2;
    int *cnt, *rowptr, *fill, *perm;
    cudaGetSymbolAddress((void**)&x_hi, g_x_hi);
    cudaGetSymbolAddress((void**)&x_lo, g_x_lo);
    cudaGetSymbolAddress((void**)&w1t_hi, g_w1t_hi);
    cudaGetSymbolAddress((void**)&w1t_lo, g_w1t_lo);
    cudaGetSymbolAddress((void**)&w2t_hi, g_w2t_hi);
    cudaGetSymbolAddress((void**)&w2t_lo, g_w2t_lo);
    cudaGetSymbolAddress((void**)&s1, g_s1);
    cudaGetSymbolAddress((void**)&h1_hi, g_h1_hi);
    cudaGetSymbolAddress((void**)&h1_lo, g_h1_lo);
    cudaGetSymbolAddress((void**)&s2, g_s2);
    cudaGetSymbolAddress((void**)&z_hi, g_z_hi);
    cudaGetSymbolAddress((void**)&z_lo, g_z_lo);
    cudaGetSymbolAddress((void**)&cnt, g_cnt);
    cudaGetSymbolAddress((void**)&rowptr, g_rowptr);
    cudaGetSymbolAddress((void**)&fill, g_fill);
    cudaGetSymbolAddress((void**)&perm, g_perm);

    // smem sizes
    const int smem_g128 = 2 * (2 * 128 * 40 + 2 * 128 * 40) * 2;   // 81920
    const int smem_g64  = 2 * (2 * 128 * 40 + 2 * 64 * 40) * 2;    // 61440
    const int smem_dec  = 4 * 128 * 72 * 2;                        // 73728 (>= 128*129*4)
    static bool attr_set = false;
    if (!attr_set) {
        cudaFuncSetAttribute(mma_gemm_db<128>, cudaFuncAttributeMaxDynamicSharedMemorySize, smem_g128);
        cudaFuncSetAttribute(mma_gemm_db<64>,  cudaFuncAttributeMaxDynamicSharedMemorySize, smem_g64);
        cudaFuncSetAttribute(decoder_sym,      cudaFuncAttributeMaxDynamicSharedMemorySize, smem_dec);
        attr_set = true;
    }

    // CSR build (independent of GEMM chain)
    zero_int<<<64, 256>>>(cnt, NN);
    hist_kernel<<<EE / 256, 256>>>(dst, cnt);
    scan_kernel<<<1, 256>>>(cnt, rowptr, fill);
    scatter_kernel<<<EE / 256, 256>>>(dst, fill, perm);

    // conversions for layer 1
    split_kernel<<<2048, 256>>>(x, x_hi, x_lo, (size_t)NN * F_IN);
    tsplit_kernel<<<512, 256>>>(W1, w1t_hi, w1t_lo, F_IN, H1);

    // 1) s1 = x @ W1   (M=16384, N=256, K=1024)
    {
        dim3 grid(H1 / 128, NN / 128);
        mma_gemm_db<128><<<grid, 256, smem_g128>>>(x_hi, x_lo, w1t_hi, w1t_lo, s1, F_IN, H1);
    }

    // 2) h1 = relu(spmm(s1)) -> split bf16 directly (no fp32 h1, no atomics)
    spmm_csr_d256<<<NN, 256>>>(rowptr, perm, src, ew, s1, h1_hi, h1_lo);

    // 3) s2 = h1 @ W2  (M=16384, N=64, K=256)
    tsplit_kernel<<<64, 256>>>(W2, w2t_hi, w2t_lo, H1, NZ);
    {
        dim3 grid(1, NN / 128);
        mma_gemm_db<64><<<grid, 256, smem_g64>>>(h1_hi, h1_lo, w2t_hi, w2t_lo, s2, H1, NZ);
    }

    // 4) z = relu(spmm(s2)) -> fp32 into d_out tail + split bf16
    spmm_csr_d64<<<NN, 64>>>(rowptr, perm, src, ew, s2, z, z_hi, z_lo);

    // 5) a_bar = z @ z.T (symmetric: upper-triangular blocks + mirrored store)
    {
        dim3 grid(NN / 128, NN / 128);
        decoder_sym<<<grid, 256, smem_dec>>>(z_hi, z_lo, a_bar);
    }
}

// round 10
// speedup vs baseline: 3.1917x; 1.1810x over previous
#include <cuda_runtime.h>
#include <cuda_bf16.h>
#include <cstdint>

// Problem constants
#define NN     16384
#define EE     262144
#define F_IN   1024
#define H1     256
#define NZ     64

// ---------------------------------------------------------------------------
// Scratch (__device__ globals; allocation-free rule)
// ---------------------------------------------------------------------------
__device__ __nv_bfloat16 g_x_hi[NN * F_IN];
__device__ __nv_bfloat16 g_x_lo[NN * F_IN];
__device__ __nv_bfloat16 g_w1t_hi[H1 * F_IN];   // W1^T [256,1024]
__device__ __nv_bfloat16 g_w1t_lo[H1 * F_IN];
__device__ __nv_bfloat16 g_w2t_hi[NZ * H1];     // W2^T [64,256]
__device__ __nv_bfloat16 g_w2t_lo[NZ * H1];
__device__ float         g_s1[NN * H1];
__device__ __nv_bfloat16 g_h1_hi[NN * H1];
__device__ __nv_bfloat16 g_h1_lo[NN * H1];
__device__ float         g_s2[NN * NZ];
__device__ __nv_bfloat16 g_z_hi[NN * NZ];
__device__ __nv_bfloat16 g_z_lo[NN * NZ];
// CSR build
__device__ int g_cnt[NN];
__device__ int g_rowptr[NN + 1];
__device__ int g_fill[NN];
__device__ int g_perm[EE];

// ---------------------------------------------------------------------------
// mma.sync / cp.async helpers (sm_80+ instructions, valid on base sm_103)
// ---------------------------------------------------------------------------
__device__ __forceinline__ void ldsm4(uint32_t& r0, uint32_t& r1, uint32_t& r2,
                                      uint32_t& r3, uint32_t saddr) {
    asm volatile("ldmatrix.sync.aligned.m8n8.x4.shared.b16 {%0,%1,%2,%3}, [%4];"
                 : "=r"(r0), "=r"(r1), "=r"(r2), "=r"(r3) : "r"(saddr));
}

__device__ __forceinline__ void mma16816(float* d, const uint32_t* a, const uint32_t* b) {
    asm volatile(
        "mma.sync.aligned.m16n8k16.row.col.f32.bf16.bf16.f32 "
        "{%0,%1,%2,%3}, {%4,%5,%6,%7}, {%8,%9}, {%0,%1,%2,%3};"
        : "+f"(d[0]), "+f"(d[1]), "+f"(d[2]), "+f"(d[3])
        : "r"(a[0]), "r"(a[1]), "r"(a[2]), "r"(a[3]), "r"(b[0]), "r"(b[1]));
}

__device__ __forceinline__ void cp16(void* sdst, const void* gsrc) {
    uint32_t sa = (uint32_t)__cvta_generic_to_shared(sdst);
    asm volatile("cp.async.cg.shared.global [%0], [%1], 16;" :: "r"(sa), "l"(gsrc));
}
#define CP_COMMIT() asm volatile("cp.async.commit_group;" ::: "memory")
#define CP_WAIT0()  asm volatile("cp.async.wait_group 0;" ::: "memory")
#define CP_WAIT1()  asm volatile("cp.async.wait_group 1;" ::: "memory")

// ---------------------------------------------------------------------------
// mma_gemm_db<BN>: C[128, BN] per block = sum_k A[m,k]*B[n,k] (both K-major,
// split bf16: D = Ah*Bh + Ah*Bl + Al*Bh). 256 threads = 8 warps (4M x 2N),
// warp tile 32 x BN/2, BK=32, cp.async double-buffered. PAD=40 rows.
// ---------------------------------------------------------------------------
template <int BN>
__global__ __launch_bounds__(256)
void mma_gemm_db(const __nv_bfloat16* __restrict__ Ah,
                 const __nv_bfloat16* __restrict__ Al,
                 const __nv_bfloat16* __restrict__ Bh,
                 const __nv_bfloat16* __restrict__ Bl,
                 float* __restrict__ C, int K, int ldC) {
    constexpr int PAD  = 40;
    constexpr int NT   = BN / 16;
    constexpr int A_ST = 2 * 128 * PAD;
    constexpr int B_ST = 2 * BN * PAD;
    constexpr int STG  = A_ST + B_ST;

    extern __shared__ __align__(16) char dyn[];
    __nv_bfloat16* sm = (__nv_bfloat16*)dyn;

    const int tid  = threadIdx.x;
    const int lane = tid & 31;
    const int warp = tid >> 5;
    const int wm   = warp & 3;
    const int wn   = warp >> 2;
    const int i0 = blockIdx.y * 128;
    const int j0 = blockIdx.x * BN;

    float acc[2][NT][4];
#pragma unroll
    for (int mi = 0; mi < 2; mi++)
#pragma unroll
        for (int ni = 0; ni < NT; ni++)
#pragma unroll
            for (int q = 0; q < 4; q++) acc[mi][ni][q] = 0.f;

    const int a_row = ((lane >> 3) & 1) * 8 + (lane & 7);
    const int a_col = (lane >> 4) * 8;
    const int b_row = (lane >> 4) * 8 + (lane & 7);
    const int b_col = ((lane >> 3) & 1) * 8;

    auto load_stage = [&](int st, int k0) {
        __nv_bfloat16* base = sm + st * STG;
#pragma unroll
        for (int t = tid; t < 128 * 4; t += 256) {
            const int r = t >> 2, c = (t & 3) * 8;
            const size_t gi = (size_t)(i0 + r) * K + k0 + c;
            cp16(base + r * PAD + c, Ah + gi);
            cp16(base + 128 * PAD + r * PAD + c, Al + gi);
        }
#pragma unroll
        for (int t = tid; t < BN * 4; t += 256) {
            const int r = t >> 2, c = (t & 3) * 8;
            const size_t gi = (size_t)(j0 + r) * K + k0 + c;
            cp16(base + A_ST + r * PAD + c, Bh + gi);
            cp16(base + A_ST + BN * PAD + r * PAD + c, Bl + gi);
        }
    };

    const int nchunks = K >> 5;
    load_stage(0, 0);
    CP_COMMIT();

    for (int ch = 0; ch < nchunks; ch++) {
        if (ch + 1 < nchunks) {
            load_stage((ch + 1) & 1, (ch + 1) << 5);
            CP_COMMIT();
            CP_WAIT1();
        } else {
            CP_WAIT0();
        }
        __syncthreads();

        __nv_bfloat16* base = sm + (ch & 1) * STG;
        __nv_bfloat16* bA[2] = {base, base + 128 * PAD};
        __nv_bfloat16* bB[2] = {base + A_ST, base + A_ST + BN * PAD};

#pragma unroll
        for (int ks = 0; ks < 2; ks++) {
            const int kk = ks * 16;
            uint32_t ah[2][4], al[2][4];
#pragma unroll
            for (int mi = 0; mi < 2; mi++) {
                const int row = wm * 32 + mi * 16 + a_row;
                ldsm4(ah[mi][0], ah[mi][1], ah[mi][2], ah[mi][3],
                      (uint32_t)__cvta_generic_to_shared(bA[0] + row * PAD + kk + a_col));
                ldsm4(al[mi][0], al[mi][1], al[mi][2], al[mi][3],
                      (uint32_t)__cvta_generic_to_shared(bA[1] + row * PAD + kk + a_col));
            }
            uint32_t bh[NT][2], bl[NT][2];
#pragma unroll
            for (int p = 0; p < NT / 2; p++) {
                const int nrow = wn * (BN / 2) + p * 16 + b_row;
                ldsm4(bh[2 * p][0], bh[2 * p][1], bh[2 * p + 1][0], bh[2 * p + 1][1],
                      (uint32_t)__cvta_generic_to_shared(bB[0] + nrow * PAD + kk + b_col));
                ldsm4(bl[2 * p][0], bl[2 * p][1], bl[2 * p + 1][0], bl[2 * p + 1][1],
                      (uint32_t)__cvta_generic_to_shared(bB[1] + nrow * PAD + kk + b_col));
            }
#pragma unroll
            for (int mi = 0; mi < 2; mi++)
#pragma unroll
                for (int ni = 0; ni < NT; ni++) {
                    mma16816(acc[mi][ni], ah[mi], bh[ni]);
                    mma16816(acc[mi][ni], ah[mi], bl[ni]);
                    mma16816(acc[mi][ni], al[mi], bh[ni]);
                }
        }
        __syncthreads();
    }

    const int er = lane >> 2;
    const int ec = (lane & 3) * 2;
#pragma unroll
    for (int mi = 0; mi < 2; mi++) {
        const int r0 = i0 + wm * 32 + mi * 16 + er;
#pragma unroll
        for (int ni = 0; ni < NT; ni++) {
            const int c0 = j0 + wn * (BN / 2) + ni * 8 + ec;
            *(float2*)&C[(size_t)r0 * ldC + c0] = make_float2(acc[mi][ni][0], acc[mi][ni][1]);
            *(float2*)&C[(size_t)(r0 + 8) * ldC + c0] = make_float2(acc[mi][ni][2], acc[mi][ni][3]);
        }
    }
}

// ---------------------------------------------------------------------------
// decoder_sym2: a_bar = z @ z.T, symmetric, A-resident panel version.
// Grid (16, 128): block (s, by) keeps A tile (panel by) in smem and loops
// bx = by+s, by+s+16, ... loading only the B tile per iteration.
// Output tile staged COLUMN-major in smem (stage[c*129+r]) so that both the
// normal and the mirrored store phases read conflict-free (banks = (c+r)%32).
// Stage aliases the B buffer. Stores use __stcs (write-once data).
// ---------------------------------------------------------------------------
__global__ __launch_bounds__(256, 2)
void decoder_sym2(const __nv_bfloat16* __restrict__ Zh,
                  const __nv_bfloat16* __restrict__ Zl,
                  float* __restrict__ C) {
    constexpr int PAD = 72;
    constexpr int TSZ = 128 * PAD;               // bf16 elems per half-tile
    extern __shared__ __align__(16) char dyn[];
    __nv_bfloat16* sA = (__nv_bfloat16*)dyn;     // hi at 0, lo at TSZ   (36864 B)
    __nv_bfloat16* sB = sA + 2 * TSZ;            // hi/lo                (36864 B)
    float* stage = (float*)sB;                   // 128*129 fp32, aliases sB

    const int by  = blockIdx.y;
    const int bx0 = by + blockIdx.x;             // blockIdx.x in [0,16)
    if (bx0 >= 128) return;
    const int i0 = by * 128;

    const int tid  = threadIdx.x;
    const int lane = tid & 31;
    const int warp = tid >> 5;
    const int wm   = warp & 3;
    const int wn   = warp >> 2;

    // resident A panel (z rows i0..i0+127, hi+lo)
    for (int t = tid; t < 128 * 8; t += 256) {
        const int r = t >> 3, c = (t & 7) * 8;
        const size_t g = (size_t)(i0 + r) * NZ + c;
        cp16(sA + r * PAD + c, Zh + g);
        cp16(sA + TSZ + r * PAD + c, Zl + g);
    }
    CP_COMMIT();

    const int a_row = ((lane >> 3) & 1) * 8 + (lane & 7);
    const int a_col = (lane >> 4) * 8;
    const int b_row = (lane >> 4) * 8 + (lane & 7);
    const int b_col = ((lane >> 3) & 1) * 8;
    const int er = lane >> 2;
    const int ec = (lane & 3) * 2;

    for (int bx = bx0; bx < 128; bx += 16) {
        const int j0 = bx * 128;
        for (int t = tid; t < 128 * 8; t += 256) {
            const int r = t >> 3, c = (t & 7) * 8;
            const size_t g = (size_t)(j0 + r) * NZ + c;
            cp16(sB + r * PAD + c, Zh + g);
            cp16(sB + TSZ + r * PAD + c, Zl + g);
        }
        CP_COMMIT();
        CP_WAIT0();
        __syncthreads();

        float acc[2][8][4];
#pragma unroll
        for (int mi = 0; mi < 2; mi++)
#pragma unroll
            for (int ni = 0; ni < 8; ni++)
#pragma unroll
                for (int q = 0; q < 4; q++) acc[mi][ni][q] = 0.f;

#pragma unroll
        for (int ks = 0; ks < 4; ks++) {
            const int kk = ks * 16;
            uint32_t ah[2][4], al[2][4];
#pragma unroll
            for (int mi = 0; mi < 2; mi++) {
                const int row = wm * 32 + mi * 16 + a_row;
                ldsm4(ah[mi][0], ah[mi][1], ah[mi][2], ah[mi][3],
                      (uint32_t)__cvta_generic_to_shared(sA + row * PAD + kk + a_col));
                ldsm4(al[mi][0], al[mi][1], al[mi][2], al[mi][3],
                      (uint32_t)__cvta_generic_to_shared(sA + TSZ + row * PAD + kk + a_col));
            }
            // register-lean B handling: one 16-row pair (2 n8-tiles) at a time
#pragma unroll
            for (int p = 0; p < 4; p++) {
                const int nrow = wn * 64 + p * 16 + b_row;
                uint32_t bh[2][2], bl[2][2];
                ldsm4(bh[0][0], bh[0][1], bh[1][0], bh[1][1],
                      (uint32_t)__cvta_generic_to_shared(sB + nrow * PAD + kk + b_col));
                ldsm4(bl[0][0], bl[0][1], bl[1][0], bl[1][1],
                      (uint32_t)__cvta_generic_to_shared(sB + TSZ + nrow * PAD + kk + b_col));
#pragma unroll
                for (int mi = 0; mi < 2; mi++)
#pragma unroll
                    for (int q = 0; q < 2; q++) {
                        mma16816(acc[mi][2 * p + q], ah[mi], bh[q]);
                        mma16816(acc[mi][2 * p + q], ah[mi], bl[q]);
                        mma16816(acc[mi][2 * p + q], al[mi], bh[q]);
                    }
            }
        }
        __syncthreads();   // all ldmatrix reads done before stage clobbers sB

        // stage column-major: stage[c*129 + r] = tile[r][c]
#pragma unroll
        for (int mi = 0; mi < 2; mi++) {
            const int r0 = wm * 32 + mi * 16 + er;
#pragma unroll
            for (int ni = 0; ni < 8; ni++) {
                const int c0 = wn * 64 + ni * 8 + ec;
                stage[c0 * 129 + r0]           = acc[mi][ni][0];
                stage[(c0 + 1) * 129 + r0]     = acc[mi][ni][1];
                stage[c0 * 129 + r0 + 8]       = acc[mi][ni][2];
                stage[(c0 + 1) * 129 + r0 + 8] = acc[mi][ni][3];
            }
        }
        __syncthreads();

        // normal store: lanes -> consecutive c (conflict-free stage reads)
        for (int t = tid; t < 128 * 128; t += 256) {
            const int c = t & 127, r = t >> 7;
            __stcs(&C[(size_t)(i0 + r) * NN + j0 + c], stage[c * 129 + r]);
        }
        // mirror store: lanes -> consecutive r (conflict-free stage reads)
        if (bx > by) {
            for (int t = tid; t < 128 * 128; t += 256) {
                const int r = t & 127, c = t >> 7;
                __stcs(&C[(size_t)(j0 + c) * NN + i0 + r], stage[c * 129 + r]);
            }
        }
        __syncthreads();   // stage reads done before next tile's B load
    }
}

// ---------------------------------------------------------------------------
// Conversion kernels
// ---------------------------------------------------------------------------
__global__ void split_kernel(const float* __restrict__ in,
                             __nv_bfloat16* __restrict__ hi,
                             __nv_bfloat16* __restrict__ lo, size_t n) {
    for (size_t i = (size_t)blockIdx.x * blockDim.x + threadIdx.x; i < n;
         i += (size_t)gridDim.x * blockDim.x) {
        float v = in[i];
        __nv_bfloat16 h = __float2bfloat16_rn(v);
        hi[i] = h;
        lo[i] = __float2bfloat16_rn(v - __bfloat162float(h));
    }
}

__global__ void tsplit_kernel(const float* __restrict__ in,
                              __nv_bfloat16* __restrict__ hi,
                              __nv_bfloat16* __restrict__ lo, int R, int C) {
    for (int i = blockIdx.x * blockDim.x + threadIdx.x; i < R * C;
         i += gridDim.x * blockDim.x) {
        int r = i / C, c = i % C;
        float v = in[i];
        __nv_bfloat16 h = __float2bfloat16_rn(v);
        hi[(size_t)c * R + r] = h;
        lo[(size_t)c * R + r] = __float2bfloat16_rn(v - __bfloat162float(h));
    }
}

// ---------------------------------------------------------------------------
// CSR build
// ---------------------------------------------------------------------------
__global__ void zero_int(int* __restrict__ p, int n) {
    for (int i = blockIdx.x * blockDim.x + threadIdx.x; i < n;
         i += gridDim.x * blockDim.x) p[i] = 0;
}

__global__ void hist_kernel(const int* __restrict__ dst, int* __restrict__ cnt) {
    int e = blockIdx.x * blockDim.x + threadIdx.x;
    if (e < EE) atomicAdd(&cnt[dst[e]], 1);
}

__global__ void scan_kernel(const int* __restrict__ cnt, int* __restrict__ rowptr,
                            int* __restrict__ fill) {
    __shared__ int ssum[256];
    const int tid = threadIdx.x;
    const int base = tid * 64;
    int s = 0;
    for (int i = 0; i < 64; i++) s += cnt[base + i];
    ssum[tid] = s;
    __syncthreads();
    if (tid == 0) {
        int run = 0;
        for (int i = 0; i < 256; i++) { int t = ssum[i]; ssum[i] = run; run += t; }
        rowptr[NN] = run;
    }
    __syncthreads();
    int run = ssum[tid];
    for (int i = 0; i < 64; i++) {
        rowptr[base + i] = run;
        fill[base + i] = run;
        run += cnt[base + i];
    }
}

__global__ void scatter_kernel(const int* __restrict__ dst, int* __restrict__ fill,
                               int* __restrict__ perm) {
    int e = blockIdx.x * blockDim.x + threadIdx.x;
    if (e < EE) {
        int slot = atomicAdd(&fill[dst[e]], 1);
        perm[slot] = e;
    }
}

// ---------------------------------------------------------------------------
// CSR SpMM (no float atomics), fused relu + bf16 split epilogues
// ---------------------------------------------------------------------------
__global__ __launch_bounds__(256)
void spmm_csr_d256(const int* __restrict__ rowptr, const int* __restrict__ perm,
                   const int* __restrict__ src, const float* __restrict__ w,
                   const float* __restrict__ in,
                   __nv_bfloat16* __restrict__ hi, __nv_bfloat16* __restrict__ lo) {
    __shared__ int   s_s[256];
    __shared__ float s_w[256];
    const int row = blockIdx.x;
    const int t = threadIdx.x;
    const int start = rowptr[row], end = rowptr[row + 1];
    float acc = 0.f;
    for (int base = start; base < end; base += 256) {
        const int m = min(256, end - base);
        if (t < m) {
            const int e = perm[base + t];
            s_s[t] = src[e];
            s_w[t] = w[e];
        }
        __syncthreads();
        for (int i = 0; i < m; i++)
            acc += s_w[i] * in[(size_t)s_s[i] * 256 + t];
        __syncthreads();
    }
    float v = fmaxf(acc, 0.f);
    __nv_bfloat16 h = __float2bfloat16_rn(v);
    hi[(size_t)row * 256 + t] = h;
    lo[(size_t)row * 256 + t] = __float2bfloat16_rn(v - __bfloat162float(h));
}

__global__ __launch_bounds__(64)
void spmm_csr_d64(const int* __restrict__ rowptr, const int* __restrict__ perm,
                  const int* __restrict__ src, const float* __restrict__ w,
                  const float* __restrict__ in, float* __restrict__ z,
                  __nv_bfloat16* __restrict__ hi, __nv_bfloat16* __restrict__ lo) {
    const int row = blockIdx.x;
    const int t = threadIdx.x;
    const int start = rowptr[row], end = rowptr[row + 1];
    float acc = 0.f;
    for (int p = start; p < end; p++) {
        const int e = perm[p];
        acc += w[e] * in[(size_t)src[e] * 64 + t];
    }
    float v = fmaxf(acc, 0.f);
    z[(size_t)row * 64 + t] = v;
    __nv_bfloat16 h = __float2bfloat16_rn(v);
    hi[(size_t)row * 64 + t] = h;
    lo[(size_t)row * 64 + t] = __float2bfloat16_rn(v - __bfloat162float(h));
}

// ---------------------------------------------------------------------------
// Launch. Inputs: x, W1, W2, edge_weight, edge_index. Out: [a_bar | z].
// ---------------------------------------------------------------------------
extern "C" void kernel_launch(void* const* d_in, const int* in_sizes, int n_in,
                              void* d_out, int out_size) {
    const float* x  = (const float*)d_in[0];
    const float* W1 = (const float*)d_in[1];
    const float* W2 = (const float*)d_in[2];
    const float* ew = (const float*)d_in[3];
    const int* eidx = (const int*)d_in[4];
    const int* src = eidx;
    const int* dst = eidx + EE;

    float* a_bar = (float*)d_out;
    float* z = (float*)d_out + ((size_t)out_size - (size_t)NN * NZ);

    __nv_bfloat16 *x_hi, *x_lo, *w1t_hi, *w1t_lo, *w2t_hi, *w2t_lo;
    __nv_bfloat16 *h1_hi, *h1_lo, *z_hi, *z_lo;
    float *s1, *s2;
    int *cnt, *rowptr, *fill, *perm;
    cudaGetSymbolAddress((void**)&x_hi, g_x_hi);
    cudaGetSymbolAddress((void**)&x_lo, g_x_lo);
    cudaGetSymbolAddress((void**)&w1t_hi, g_w1t_hi);
    cudaGetSymbolAddress((void**)&w1t_lo, g_w1t_lo);
    cudaGetSymbolAddress((void**)&w2t_hi, g_w2t_hi);
    cudaGetSymbolAddress((void**)&w2t_lo, g_w2t_lo);
    cudaGetSymbolAddress((void**)&s1, g_s1);
    cudaGetSymbolAddress((void**)&h1_hi, g_h1_hi);
    cudaGetSymbolAddress((void**)&h1_lo, g_h1_lo);
    cudaGetSymbolAddress((void**)&s2, g_s2);
    cudaGetSymbolAddress((void**)&z_hi, g_z_hi);
    cudaGetSymbolAddress((void**)&z_lo, g_z_lo);
    cudaGetSymbolAddress((void**)&cnt, g_cnt);
    cudaGetSymbolAddress((void**)&rowptr, g_rowptr);
    cudaGetSymbolAddress((void**)&fill, g_fill);
    cudaGetSymbolAddress((void**)&perm, g_perm);

    // one-time setup (host objects only; no device memory)
    static cudaStream_t side = nullptr;
    static cudaEvent_t evFork = nullptr, evJoin = nullptr;
    static bool attr_set = false;
    const int smem_g128 = 2 * (2 * 128 * 40 + 2 * 128 * 40) * 2;   // 81920
    const int smem_g64  = 2 * (2 * 128 * 40 + 2 * 64 * 40) * 2;    // 61440
    const int smem_dec  = 2 * 128 * 72 * 2 + 128 * 129 * 4;        // 36864 + 66048 = 102912
    if (!attr_set) {
        cudaFuncSetAttribute(mma_gemm_db<128>, cudaFuncAttributeMaxDynamicSharedMemorySize, smem_g128);
        cudaFuncSetAttribute(mma_gemm_db<64>,  cudaFuncAttributeMaxDynamicSharedMemorySize, smem_g64);
        cudaFuncSetAttribute(decoder_sym2,     cudaFuncAttributeMaxDynamicSharedMemorySize, smem_dec);
        cudaStreamCreateWithFlags(&side, cudaStreamNonBlocking);
        cudaEventCreateWithFlags(&evFork, cudaEventDisableTiming);
        cudaEventCreateWithFlags(&evJoin, cudaEventDisableTiming);
        attr_set = true;
    }

    // ---- fork: CSR build + W2 transpose-split on side stream ----
    cudaEventRecord(evFork, 0);
    cudaStreamWaitEvent(side, evFork, 0);
    zero_int<<<64, 256, 0, side>>>(cnt, NN);
    hist_kernel<<<EE / 256, 256, 0, side>>>(dst, cnt);
    scan_kernel<<<1, 256, 0, side>>>(cnt, rowptr, fill);
    scatter_kernel<<<EE / 256, 256, 0, side>>>(dst, fill, perm);
    tsplit_kernel<<<64, 256, 0, side>>>(W2, w2t_hi, w2t_lo, H1, NZ);
    cudaEventRecord(evJoin, side);

    // ---- main chain ----
    split_kernel<<<2048, 256>>>(x, x_hi, x_lo, (size_t)NN * F_IN);
    tsplit_kernel<<<512, 256>>>(W1, w1t_hi, w1t_lo, F_IN, H1);

    // 1) s1 = x @ W1   (M=16384, N=256, K=1024)
    {
        dim3 grid(H1 / 128, NN / 128);
        mma_gemm_db<128><<<grid, 256, smem_g128>>>(x_hi, x_lo, w1t_hi, w1t_lo, s1, F_IN, H1);
    }

    // join: need CSR (and W2 split before gemm2)
    cudaStreamWaitEvent(0, evJoin, 0);

    // 2) h1 = relu(spmm(s1)) -> split bf16 directly
    spmm_csr_d256<<<NN, 256>>>(rowptr, perm, src, ew, s1, h1_hi, h1_lo);

    // 3) s2 = h1 @ W2  (M=16384, N=64, K=256)
    {
        dim3 grid(1, NN / 128);
        mma_gemm_db<64><<<grid, 256, smem_g64>>>(h1_hi, h1_lo, w2t_hi, w2t_lo, s2, H1, NZ);
    }

    // 4) z = relu(spmm(s2)) -> fp32 into d_out tail + split bf16
    spmm_csr_d64<<<NN, 64>>>(rowptr, perm, src, ew, s2, z, z_hi, z_lo);

    // 5) a_bar = z @ z.T (symmetric, A-resident panels)
    {
        dim3 grid(16, 128);
        decoder_sym2<<<grid, 256, smem_dec>>>(z_hi, z_lo, a_bar);
    }
}